// round 17
// baseline (speedup 1.0000x reference)
#include <cuda_runtime.h>
#include <cuda_bf16.h>
#include <cstdint>

// Problem constants (fixed shapes): B=4, C=64, H=W=128, O=64, K=3
#define BB 4
#define CC 64
#define HH 128
#define WW 128
#define OO 64
#define HWP (HH*WW)          // 16384
#define NPIX (BB*HWP)        // 65536
#define TILE 128             // pixels per block (one image row)
#define NBLK (NPIX / TILE)   // 512
#define BPITCH 144           // smem row pitch bytes (72 bf16): conflict-free ldmatrix

typedef unsigned long long u64;
typedef unsigned int u32;

// ---------------- scratch (static device globals; no allocation) ----------------
__device__ float  g_xh[(size_t)NPIX * CC];       // x in NHWC: [b][h][w][c]   16 MB
__device__ __align__(16) __nv_bfloat16 g_xbh[(size_t)NPIX * CC];  // x hi bf16 NHWC  8 MB
__device__ __align__(16) __nv_bfloat16 g_xbl[(size_t)NPIX * CC];  // x lo bf16 NHWC  8 MB
__device__ float4 g_smp[(size_t)9 * NPIX];       // per (tap, pixel): ys, xs, mask
__device__ float  g_raw[(size_t)NPIX * OO];      // pre-BN conv output, [pix][o]
__device__ __align__(16) unsigned char g_wth[9 * OO * BPITCH];   // main weight hi bf16 [tap][o][c]
__device__ __align__(16) unsigned char g_wtl[9 * OO * BPITCH];   // main weight lo bf16
__device__ __align__(16) unsigned char g_owth[9 * 32 * BPITCH];  // offset weight hi bf16 [tap][n][c]
__device__ __align__(16) unsigned char g_owtl[9 * 32 * BPITCH];  // offset weight lo bf16
__device__ float  g_psum[NBLK * OO];             // BN partial sums (per k_main block)
__device__ float  g_psq[NBLK * OO];              // BN partial sumsq
__device__ float  g_scale[OO];
__device__ float  g_shift[OO];

// ---------------- mma/ldmatrix/cp.async helpers (baseline PTX, works on sm_100) ----------------
__device__ __forceinline__ u32 smem_u32(const void* p) {
    u32 a;
    asm("{ .reg .u64 t; cvta.to.shared.u64 t, %1; cvt.u32.u64 %0, t; }" : "=r"(a) : "l"(p));
    return a;
}
__device__ __forceinline__ void ldsm4(u32* r, u32 addr) {
    asm volatile("ldmatrix.sync.aligned.m8n8.x4.shared.b16 {%0,%1,%2,%3}, [%4];"
        : "=r"(r[0]), "=r"(r[1]), "=r"(r[2]), "=r"(r[3]) : "r"(addr));
}
__device__ __forceinline__ void mma16816(float* c, const u32* a, u32 b0, u32 b1) {
    asm volatile(
        "mma.sync.aligned.m16n8k16.row.col.f32.bf16.bf16.f32 "
        "{%0,%1,%2,%3}, {%4,%5,%6,%7}, {%8,%9}, {%0,%1,%2,%3};"
        : "+f"(c[0]), "+f"(c[1]), "+f"(c[2]), "+f"(c[3])
        : "r"(a[0]), "r"(a[1]), "r"(a[2]), "r"(a[3]), "r"(b0), "r"(b1));
}
__device__ __forceinline__ void cpasync16(u32 smem, const void* g) {
    asm volatile("cp.async.cg.shared.global [%0], [%1], 16;" :: "r"(smem), "l"(g));
}
#define CPCOMMIT() asm volatile("cp.async.commit_group;" ::: "memory")
#define CPWAIT0()  asm volatile("cp.async.wait_group 0;" ::: "memory")

// split a float4 pair (8 ch) via TRUNCATION hi + rn lo, store to pitched rows.
// hi = bit-truncated bf16 (PRMT pair-pack); lo = v - hi, rn-converted. |lo| <= 2^-8 |v|.
__device__ __forceinline__ void splitStore(float4 V0, float4 V1, char* rowH, char* rowL, int j) {
    u32 u0 = __float_as_uint(V0.x), u1 = __float_as_uint(V0.y);
    u32 u2 = __float_as_uint(V0.z), u3 = __float_as_uint(V0.w);
    u32 u4 = __float_as_uint(V1.x), u5 = __float_as_uint(V1.y);
    u32 u6 = __float_as_uint(V1.z), u7 = __float_as_uint(V1.w);
    u32 h01 = __byte_perm(u0, u1, 0x7632);
    u32 h23 = __byte_perm(u2, u3, 0x7632);
    u32 h45 = __byte_perm(u4, u5, 0x7632);
    u32 h67 = __byte_perm(u6, u7, 0x7632);
    float l0 = V0.x - __uint_as_float(u0 & 0xFFFF0000u);
    float l1 = V0.y - __uint_as_float(u1 & 0xFFFF0000u);
    float l2 = V0.z - __uint_as_float(u2 & 0xFFFF0000u);
    float l3 = V0.w - __uint_as_float(u3 & 0xFFFF0000u);
    float l4 = V1.x - __uint_as_float(u4 & 0xFFFF0000u);
    float l5 = V1.y - __uint_as_float(u5 & 0xFFFF0000u);
    float l6 = V1.z - __uint_as_float(u6 & 0xFFFF0000u);
    float l7 = V1.w - __uint_as_float(u7 & 0xFFFF0000u);
    __nv_bfloat162 q01 = __floats2bfloat162_rn(l0, l1);
    __nv_bfloat162 q23 = __floats2bfloat162_rn(l2, l3);
    __nv_bfloat162 q45 = __floats2bfloat162_rn(l4, l5);
    __nv_bfloat162 q67 = __floats2bfloat162_rn(l6, l7);
    u32 r01, r23, r45, r67;
    memcpy(&r01, &q01, 4); memcpy(&r23, &q23, 4);
    memcpy(&r45, &q45, 4); memcpy(&r67, &q67, 4);
    *(uint2*)(rowH + 8 * j)      = make_uint2(h01, h23);
    *(uint2*)(rowH + 64 + 8 * j) = make_uint2(h45, h67);
    *(uint2*)(rowL + 8 * j)      = make_uint2(r01, r23);
    *(uint2*)(rowL + 64 + 8 * j) = make_uint2(r45, r67);
}

// k_main smem layout: double-buffered A hi/lo + B hi/lo
#define BUFSZ   55296
#define SMA_H(b) ((b) * BUFSZ + 0)
#define SMA_L(b) ((b) * BUFSZ + TILE * BPITCH)
#define SMB_H(b) ((b) * BUFSZ + 2 * TILE * BPITCH)
#define SMB_L(b) ((b) * BUFSZ + 2 * TILE * BPITCH + OO * BPITCH)
#define SM_TOT  (2 * BUFSZ)                                 // 110592

// k_offmma smem layout (single buffer)
#define OS_AH 0
#define OS_AL (TILE * BPITCH)            // 18432
#define OS_BH (2 * TILE * BPITCH)        // 36864
#define OS_BL (OS_BH + 32 * BPITCH)      // 41472
#define OS_TOT (OS_BL + 32 * BPITCH)     // 46080
#define CPITCH 34                        // epilogue C smem pitch (floats)

// ---------------- K0: NCHW -> NHWC transpose + bf16 hi/lo pre-split ----------------
__global__ void k_transpose(const float* __restrict__ x) {
    __shared__ float t[32][33];
    int b  = blockIdx.z;
    int c0 = blockIdx.y * 32;
    int p0 = blockIdx.x * 32;
    int tx = threadIdx.x, ty = threadIdx.y;
    #pragma unroll
    for (int j = 0; j < 4; j++) {
        int c = c0 + ty + j * 8;
        t[ty + j * 8][tx] = x[((size_t)(b * CC + c)) * HWP + p0 + tx];
    }
    __syncthreads();
    #pragma unroll
    for (int j = 0; j < 4; j++) {
        int p = p0 + ty + j * 8;
        float v = t[tx][ty + j * 8];
        size_t idx = ((size_t)(b * HWP + p)) * CC + c0 + tx;
        g_xh[idx] = v;
        u32 u = __float_as_uint(v);
        *(unsigned short*)&g_xbh[idx] = (unsigned short)(u >> 16);
        g_xbl[idx] = __float2bfloat16_rn(v - __uint_as_float(u & 0xFFFF0000u));
    }
}

// ---------------- Kprep: weight relayouts (bf16 hi/lo split, pitched) ----------------
__global__ void k_prep(const float* __restrict__ wmain, const float* __restrict__ ow) {
    int i = blockIdx.x * 256 + threadIdx.x;
    if (i < 9 * OO * CC) {
        int k = i >> 12;           // tap
        int r = i & 4095;
        int o = r >> 6, c = r & 63;
        float w = wmain[o * 576 + c * 9 + k];
        u32 u = __float_as_uint(w);
        float lo = w - __uint_as_float(u & 0xFFFF0000u);
        size_t off = (size_t)k * OO * BPITCH + o * BPITCH + c * 2;
        *(unsigned short*)(g_wth + off) = (unsigned short)(u >> 16);
        *(__nv_bfloat16*)(g_wtl + off) = __float2bfloat16_rn(lo);
    }
    if (i < 9 * 32 * CC) {         // offset conv weights: [tap][n(pad32)][c]
        int k = i >> 11;           // / 2048
        int r = i & 2047;
        int n = r >> 6, c = r & 63;
        float w = (n < 27) ? ow[n * 576 + c * 9 + k] : 0.0f;
        u32 u = __float_as_uint(w);
        float lo = w - __uint_as_float(u & 0xFFFF0000u);
        size_t off = (size_t)k * 32 * BPITCH + n * BPITCH + c * 2;
        *(unsigned short*)(g_owth + off) = (unsigned short)(u >> 16);
        *(__nv_bfloat16*)(g_owtl + off) = __float2bfloat16_rn(lo);
    }
}

// ---------------- K1: offset conv via mma.sync (A = pre-split bf16 x) ----------------
__global__ __launch_bounds__(256, 3) void k_offmma(const float* __restrict__ ob) {
    extern __shared__ __align__(16) char smc[];
    u32 sb = smem_u32(smc);
    int t = threadIdx.x;
    int w = t >> 5, lane = t & 31;
    int pix0 = blockIdx.x * TILE;
    int b = pix0 >> 14;
    int h = (pix0 >> 7) & 127;
    const __nv_bfloat16* xbh = g_xbh + (size_t)(b << 14) * CC;
    const __nv_bfloat16* xbl = g_xbl + (size_t)(b << 14) * CC;

    int gg = t >> 3, j = t & 7;
    int mb = (w & 3) * 32;
    int nbh = (w >> 2) * 16;

    float acc[2][2][4];
    #pragma unroll
    for (int mi = 0; mi < 2; mi++)
        #pragma unroll
        for (int ni = 0; ni < 2; ni++)
            #pragma unroll
            for (int q = 0; q < 4; q++) acc[mi][ni][q] = 0.0f;

    u32 aAddr[2];
    #pragma unroll
    for (int mi = 0; mi < 2; mi++)
        aAddr[mi] = sb + OS_AH + (mb + 16 * mi + (lane & 15)) * BPITCH + (lane >> 4) * 16;
    u32 bAddr;
    {
        int nrow = nbh + ((lane >> 4) & 1) * 8 + (lane & 7);
        bAddr = sb + OS_BH + nrow * BPITCH + ((lane >> 3) & 1) * 16;
    }

    #pragma unroll 1
    for (int k = 0; k < 9; k++) {
        __syncthreads();
        {
            const uint4* sh = (const uint4*)(g_owth + (size_t)k * 32 * BPITCH);
            const uint4* sl = (const uint4*)(g_owtl + (size_t)k * 32 * BPITCH);
            uint4* dh = (uint4*)(smc + OS_BH);
            uint4* dl = (uint4*)(smc + OS_BL);
            if (t < 288 - 256) { dh[t + 256] = sh[t + 256]; dl[t + 256] = sl[t + 256]; }
            dh[t] = sh[t]; dl[t] = sl[t];
        }
        int y = h + k / 3 - 1;
        bool vy = ((unsigned)y < 128u);
        #pragma unroll 1
        for (int s = 0; s < 4; s++) {
            int p = gg * 4 + s;
            int x = p + (k % 3) - 1;
            bool v = vy && ((unsigned)x < 128u);
            uint2 H0 = make_uint2(0u, 0u), H1 = H0, L0 = H0, L1 = H0;
            if (v) {
                const char* ph = (const char*)(xbh + ((y << 7) + x) * CC) + 8 * j;
                const char* pl = (const char*)(xbl + ((y << 7) + x) * CC) + 8 * j;
                H0 = *(const uint2*)ph;  H1 = *(const uint2*)(ph + 64);
                L0 = *(const uint2*)pl;  L1 = *(const uint2*)(pl + 64);
            }
            char* rowH = smc + OS_AH + p * BPITCH;
            char* rowL = smc + OS_AL + p * BPITCH;
            *(uint2*)(rowH + 8 * j)      = H0;
            *(uint2*)(rowH + 64 + 8 * j) = H1;
            *(uint2*)(rowL + 8 * j)      = L0;
            *(uint2*)(rowL + 64 + 8 * j) = L1;
        }
        __syncthreads();

        #pragma unroll
        for (int ks = 0; ks < 4; ks++) {
            u32 ah[2][4], al[2][4];
            #pragma unroll
            for (int mi = 0; mi < 2; mi++) {
                ldsm4(ah[mi], aAddr[mi] + ks * 32);
                ldsm4(al[mi], aAddr[mi] + ks * 32 + (OS_AL - OS_AH));
            }
            u32 bh[4], bl[4];
            ldsm4(bh, bAddr + ks * 32);
            ldsm4(bl, bAddr + ks * 32 + (OS_BL - OS_BH));
            #pragma unroll
            for (int mi = 0; mi < 2; mi++) {
                mma16816(acc[mi][0], ah[mi], bh[0], bh[1]);
                mma16816(acc[mi][0], ah[mi], bl[0], bl[1]);
                mma16816(acc[mi][0], al[mi], bh[0], bh[1]);
                mma16816(acc[mi][1], ah[mi], bh[2], bh[3]);
                mma16816(acc[mi][1], ah[mi], bl[2], bl[3]);
                mma16816(acc[mi][1], al[mi], bh[2], bh[3]);
            }
        }
    }
    __syncthreads();

    float* Csm = (float*)smc;
    int er = lane >> 2, ec = (lane & 3) * 2;
    #pragma unroll
    for (int mi = 0; mi < 2; mi++) {
        #pragma unroll
        for (int ni = 0; ni < 2; ni++) {
            int row = mb + 16 * mi + er;
            int col = nbh + 8 * ni + ec;
            *(float2*)&Csm[row * CPITCH + col]       = make_float2(acc[mi][ni][0], acc[mi][ni][1]);
            *(float2*)&Csm[(row + 8) * CPITCH + col] = make_float2(acc[mi][ni][2], acc[mi][ni][3]);
        }
    }
    __syncthreads();

    if (t < TILE) {
        int pix = pix0 + t;
        float c[27];
        #pragma unroll
        for (int i = 0; i < 27; i++) c[i] = Csm[t * CPITCH + i] + ob[i];
        #pragma unroll
        for (int k = 0; k < 9; k++) {
            float ys = (float)(h - 1 + k / 3) + c[2 * k];
            float xs = (float)(t - 1 + k % 3) + c[2 * k + 1];
            float mk = 1.0f / (1.0f + expf(-c[18 + k]));
            g_smp[(size_t)k * NPIX + pix] = make_float4(ys, xs, mk, 0.0f);
        }
    }
}

// ---------------- gather helpers for k_main ----------------
struct Pref {
    float4 a00, a01, a10, a11, b00, b01, b10, b11;
    float w00, w01, w10, w11;
};
__device__ __forceinline__ Pref issueGather(const float* xb, float4 sp, int j) {
    Pref P;
    float y0f = floorf(sp.x), x0f = floorf(sp.y);
    float fy = sp.x - y0f, fx = sp.y - x0f;
    int y0 = (int)y0f, x0 = (int)x0f;
    float m = sp.z, gy = 1.0f - fy, gx = 1.0f - fx;
    bool vy0 = ((unsigned)y0 < 128u), vy1 = ((unsigned)(y0 + 1) < 128u);
    bool vx0 = ((unsigned)x0 < 128u), vx1 = ((unsigned)(x0 + 1) < 128u);
    P.w00 = (vy0 && vx0) ? gy * gx * m : 0.0f;
    P.w01 = (vy0 && vx1) ? gy * fx * m : 0.0f;
    P.w10 = (vy1 && vx0) ? fy * gx * m : 0.0f;
    P.w11 = (vy1 && vx1) ? fy * fx * m : 0.0f;
    int r0 = (vy0 ? y0 : 0) << 7, r1 = (vy1 ? (y0 + 1) : 0) << 7;
    int cA = vx0 ? x0 : 0, cBx = vx1 ? (x0 + 1) : 0;
    const float* p00 = xb + (r0 + cA) * CC + 4 * j;
    const float* p01 = xb + (r0 + cBx) * CC + 4 * j;
    const float* p10 = xb + (r1 + cA) * CC + 4 * j;
    const float* p11 = xb + (r1 + cBx) * CC + 4 * j;
    P.a00 = *(const float4*)p00;        P.a01 = *(const float4*)p01;
    P.a10 = *(const float4*)p10;        P.a11 = *(const float4*)p11;
    P.b00 = *(const float4*)(p00 + 32); P.b01 = *(const float4*)(p01 + 32);
    P.b10 = *(const float4*)(p10 + 32); P.b11 = *(const float4*)(p11 + 32);
    return P;
}
__device__ __forceinline__ void retireGather(const Pref& P, char* rowH, char* rowL, int j) {
    float4 V0, V1;
    V0.x = fmaf(P.w00, P.a00.x, fmaf(P.w01, P.a01.x, fmaf(P.w10, P.a10.x, P.w11 * P.a11.x)));
    V0.y = fmaf(P.w00, P.a00.y, fmaf(P.w01, P.a01.y, fmaf(P.w10, P.a10.y, P.w11 * P.a11.y)));
    V0.z = fmaf(P.w00, P.a00.z, fmaf(P.w01, P.a01.z, fmaf(P.w10, P.a10.z, P.w11 * P.a11.z)));
    V0.w = fmaf(P.w00, P.a00.w, fmaf(P.w01, P.a01.w, fmaf(P.w10, P.a10.w, P.w11 * P.a11.w)));
    V1.x = fmaf(P.w00, P.b00.x, fmaf(P.w01, P.b01.x, fmaf(P.w10, P.b10.x, P.w11 * P.b11.x)));
    V1.y = fmaf(P.w00, P.b00.y, fmaf(P.w01, P.b01.y, fmaf(P.w10, P.b10.y, P.w11 * P.b11.y)));
    V1.z = fmaf(P.w00, P.b00.z, fmaf(P.w01, P.b01.z, fmaf(P.w10, P.b10.z, P.w11 * P.b11.z)));
    V1.w = fmaf(P.w00, P.b00.w, fmaf(P.w01, P.b01.w, fmaf(P.w10, P.b10.w, P.w11 * P.b11.w)));
    splitStore(V0, V1, rowH, rowL, j);
}

// ---------------- K2: pipelined (1 sync/tap) + sp depth-2 prefetch + cp.async B ----------------
__global__ __launch_bounds__(256, 2) void k_main() {
    extern __shared__ __align__(16) char smc[];
    u32 sb = smem_u32(smc);

    int t = threadIdx.x;
    int w = t >> 5, lane = t & 31;
    int pix0 = blockIdx.x * TILE;
    int b = pix0 >> 14;
    const float* xb = g_xh + (size_t)(b << 14) * CC;

    int gg = t >> 3;   // gather group 0..31 -> pixels 4gg..4gg+3
    int j  = t & 7;    // lane in group -> channels 4j..4j+3 and 32+4j..32+4j+3

    int mb = (w & 3) * 32;    // warp m base (pixels)
    int nb = (w >> 2) * 32;   // warp n base (outputs)

    float acc[2][4][4];
    #pragma unroll
    for (int mi = 0; mi < 2; mi++)
        #pragma unroll
        for (int ni = 0; ni < 4; ni++)
            #pragma unroll
            for (int q = 0; q < 4; q++) acc[mi][ni][q] = 0.0f;

    u32 aOff[2];
    #pragma unroll
    for (int mi = 0; mi < 2; mi++)
        aOff[mi] = (mb + 16 * mi + (lane & 15)) * BPITCH + (lane >> 4) * 16;
    u32 bOff[2];
    #pragma unroll
    for (int half = 0; half < 2; half++) {
        int nrow = nb + 16 * half + ((lane >> 4) & 1) * 8 + (lane & 7);
        bOff[half] = nrow * BPITCH + ((lane >> 3) & 1) * 16;
    }

    // ---- prologue: B0 copy + gather tap 0 into buf0 + prefetch sp for tap 1 ----
    float4 spN[4];
    {
        const uint4* sh = (const uint4*)g_wth;
        const uint4* sl = (const uint4*)g_wtl;
        uint4* dh = (uint4*)(smc + SMB_H(0));
        uint4* dl = (uint4*)(smc + SMB_L(0));
        dh[t] = sh[t]; dl[t] = sl[t];
        dh[t + 256] = sh[t + 256]; dl[t + 256] = sl[t + 256];
        if (t < 64) { dh[t + 512] = sh[t + 512]; dl[t + 512] = sl[t + 512]; }
        #pragma unroll 1
        for (int s = 0; s < 4; s++) {
            int p = gg * 4 + s;
            float4 sp = g_smp[pix0 + p];
            Pref P = issueGather(xb, sp, j);
            retireGather(P, smc + SMA_H(0) + p * BPITCH, smc + SMA_L(0) + p * BPITCH, j);
        }
        #pragma unroll
        for (int s = 0; s < 4; s++)
            spN[s] = g_smp[(size_t)1 * NPIX + pix0 + gg * 4 + s];
    }
    __syncthreads();

    // ---- pipelined main loop ----
    #pragma unroll 1
    for (int k = 0; k < 9; k++) {
        int cur = k & 1, nxt = cur ^ 1;
        bool pre = (k < 8);
        u32 baseAH = sb + SMA_H(cur), baseAL = sb + SMA_L(cur);
        u32 baseBH = sb + SMB_H(cur), baseBL = sb + SMB_L(cur);
        char* rowHb = smc + SMA_H(nxt);
        char* rowLb = smc + SMA_L(nxt);

        // --- async B prefetch for tap k+1 into next buffers ---
        if (pre) {
            const char* shh = (const char*)(g_wth + (size_t)(k + 1) * OO * BPITCH);
            const char* sll = (const char*)(g_wtl + (size_t)(k + 1) * OO * BPITCH);
            u32 dh = sb + SMB_H(nxt), dl = sb + SMB_L(nxt);
            #pragma unroll
            for (int i = 0; i < 3; i++) {
                int idx = t + i * 256;
                if (idx < 576) {
                    cpasync16(dh + idx * 16, shh + idx * 16);
                    cpasync16(dl + idx * 16, sll + idx * 16);
                }
            }
            CPCOMMIT();
        }

        #pragma unroll
        for (int s = 0; s < 4; s++) {
            int p = gg * 4 + s;
            // --- issue gather for tap k+1 using prefetched coords ---
            Pref P;
            if (pre) P = issueGather(xb, spN[s], j);
            // --- refill coord slot with tap k+2 (consumed next tap) ---
            if (k < 7) spN[s] = g_smp[(size_t)(k + 2) * NPIX + pix0 + p];

            // --- GEMM step ks = s on current buffers ---
            {
                u32 ah[2][4], al[2][4];
                #pragma unroll
                for (int mi = 0; mi < 2; mi++) {
                    ldsm4(ah[mi], baseAH + aOff[mi] + s * 32);
                    ldsm4(al[mi], baseAL + aOff[mi] + s * 32);
                }
                #pragma unroll
                for (int half = 0; half < 2; half++) {
                    u32 bh[4], bl[4];
                    ldsm4(bh, baseBH + bOff[half] + s * 32);
                    ldsm4(bl, baseBL + bOff[half] + s * 32);
                    #pragma unroll
                    for (int mi = 0; mi < 2; mi++) {
                        mma16816(acc[mi][2 * half],     ah[mi], bh[0], bh[1]);
                        mma16816(acc[mi][2 * half],     ah[mi], bl[0], bl[1]);
                        mma16816(acc[mi][2 * half],     al[mi], bh[0], bh[1]);
                        mma16816(acc[mi][2 * half + 1], ah[mi], bh[2], bh[3]);
                        mma16816(acc[mi][2 * half + 1], ah[mi], bl[2], bl[3]);
                        mma16816(acc[mi][2 * half + 1], al[mi], bh[2], bh[3]);
                    }
                }
            }

            // --- retire gather into next A buffers ---
            if (pre) retireGather(P, rowHb + p * BPITCH, rowLb + p * BPITCH, j);
        }
        if (pre) CPWAIT0();
        __syncthreads();
    }

    // ---- epilogue: fragment -> g_raw ----
    int er = lane >> 2, ec = (lane & 3) * 2;
    #pragma unroll
    for (int mi = 0; mi < 2; mi++) {
        #pragma unroll
        for (int ni = 0; ni < 4; ni++) {
            int pix = pix0 + mb + 16 * mi + er;
            int o = nb + 8 * ni + ec;
            *(float2*)(g_raw + (size_t)pix * OO + o)       = make_float2(acc[mi][ni][0], acc[mi][ni][1]);
            *(float2*)(g_raw + (size_t)(pix + 8) * OO + o) = make_float2(acc[mi][ni][2], acc[mi][ni][3]);
        }
    }

    // ---- fused BN partial stats (fixed-order shfl tree + fixed warp order) ----
    float ps[8], pq[8];
    #pragma unroll
    for (int ni = 0; ni < 4; ni++) {
        float s0 = 0.f, q0 = 0.f, s1 = 0.f, q1 = 0.f;
        #pragma unroll
        for (int mi = 0; mi < 2; mi++) {
            float a0 = acc[mi][ni][0], a1 = acc[mi][ni][1];
            float a2 = acc[mi][ni][2], a3 = acc[mi][ni][3];
            s0 += a0 + a2;  q0 += a0 * a0 + a2 * a2;
            s1 += a1 + a3;  q1 += a1 * a1 + a3 * a3;
        }
        ps[2 * ni] = s0; pq[2 * ni] = q0;
        ps[2 * ni + 1] = s1; pq[2 * ni + 1] = q1;
    }
    #pragma unroll
    for (int off = 4; off <= 16; off <<= 1) {
        #pragma unroll
        for (int i = 0; i < 8; i++) {
            ps[i] += __shfl_xor_sync(0xFFFFFFFF, ps[i], off);
            pq[i] += __shfl_xor_sync(0xFFFFFFFF, pq[i], off);
        }
    }
    float* sms = (float*)smc;          // [8][32]
    float* smq = sms + 256;            // [8][32]
    if (lane < 4) {
        #pragma unroll
        for (int ni = 0; ni < 4; ni++) {
            int lo = 8 * ni + lane * 2;
            sms[w * 32 + lo]     = ps[2 * ni];
            sms[w * 32 + lo + 1] = ps[2 * ni + 1];
            smq[w * 32 + lo]     = pq[2 * ni];
            smq[w * 32 + lo + 1] = pq[2 * ni + 1];
        }
    }
    __syncthreads();
    if (t < 64) {
        int grp = t >> 5, wo = t & 31;
        float S = sms[(grp * 4 + 0) * 32 + wo] + sms[(grp * 4 + 1) * 32 + wo]
                + sms[(grp * 4 + 2) * 32 + wo] + sms[(grp * 4 + 3) * 32 + wo];
        float Q = smq[(grp * 4 + 0) * 32 + wo] + smq[(grp * 4 + 1) * 32 + wo]
                + smq[(grp * 4 + 2) * 32 + wo] + smq[(grp * 4 + 3) * 32 + wo];
        g_psum[blockIdx.x * OO + t] = S;
        g_psq[blockIdx.x * OO + t]  = Q;
    }
}

// ---------------- K3: finalize stats -> scale/shift ----------------
__global__ void k_stats2(const float* __restrict__ gamma, const float* __restrict__ beta) {
    __shared__ float ss[256], sq[256];
    int ch = blockIdx.x, t = threadIdx.x;
    ss[t] = g_psum[t * OO + ch] + g_psum[(t + 256) * OO + ch];
    sq[t] = g_psq[t * OO + ch]  + g_psq[(t + 256) * OO + ch];
    __syncthreads();
    for (int s = 128; s > 0; s >>= 1) {
        if (t < s) { ss[t] += ss[t + s]; sq[t] += sq[t + s]; }
        __syncthreads();
    }
    if (t == 0) {
        const float inv_n = 1.0f / (float)NPIX;
        float mean = ss[0] * inv_n;
        float var  = sq[0] * inv_n - mean * mean;
        float inv  = rsqrtf(var + 1e-5f);
        float sc   = gamma[ch] * inv;
        g_scale[ch] = sc;
        g_shift[ch] = beta[ch] - mean * sc;
        // conv bias cancels exactly inside batch-norm (per-channel constant)
    }
}

// ---------------- K4: BN + ReLU + NHWC->NCHW ----------------
__global__ void k_bnout(float* __restrict__ out) {
    __shared__ float s[64][65];
    __shared__ float scs[64], shs[64];
    int t = threadIdx.x;
    if (t < 64) { scs[t] = g_scale[t]; shs[t] = g_shift[t]; }
    __syncthreads();
    int pix0 = blockIdx.x * 64;
    int b = pix0 >> 14;
    int pl = pix0 & 16383;
    #pragma unroll
    for (int j = 0; j < 4; j++) {
        int idx = t + j * 256;
        int p = idx >> 4;      // 0..63 local pixel
        int q = idx & 15;      // float4 group of channels
        float4 v = *(const float4*)(g_raw + (size_t)(pix0 + p) * OO + q * 4);
        int c = q * 4;
        s[c + 0][p] = fmaxf(fmaf(v.x, scs[c + 0], shs[c + 0]), 0.0f);
        s[c + 1][p] = fmaxf(fmaf(v.y, scs[c + 1], shs[c + 1]), 0.0f);
        s[c + 2][p] = fmaxf(fmaf(v.z, scs[c + 2], shs[c + 2]), 0.0f);
        s[c + 3][p] = fmaxf(fmaf(v.w, scs[c + 3], shs[c + 3]), 0.0f);
    }
    __syncthreads();
    #pragma unroll
    for (int j = 0; j < 4; j++) {
        int idx = t + j * 256;
        int o = idx >> 4;
        int q = idx & 15;
        float4 r = make_float4(s[o][q * 4], s[o][q * 4 + 1], s[o][q * 4 + 2], s[o][q * 4 + 3]);
        *(float4*)(out + (size_t)(b * OO + o) * HWP + pl + q * 4) = r;
    }
}

// ---------------- launch ----------------
extern "C" void kernel_launch(void* const* d_in, const int* in_sizes, int n_in,
                              void* d_out, int out_size) {
    const float* x     = (const float*)d_in[0];
    const float* ow    = (const float*)d_in[1];
    const float* ob    = (const float*)d_in[2];
    const float* wt    = (const float*)d_in[3];
    // d_in[4] = bias: cancels exactly in batch norm, unused
    const float* gamma = (const float*)d_in[5];
    const float* beta  = (const float*)d_in[6];
    float* out = (float*)d_out;

    cudaFuncSetAttribute(k_offmma, cudaFuncAttributeMaxDynamicSharedMemorySize, OS_TOT);
    cudaFuncSetAttribute(k_main, cudaFuncAttributeMaxDynamicSharedMemorySize, SM_TOT);

    k_transpose<<<dim3(HWP / 32, CC / 32, BB), dim3(32, 8)>>>(x);
    k_prep<<<(9 * OO * CC + 255) / 256, 256>>>(wt, ow);
    k_offmma<<<NBLK, 256, OS_TOT>>>(ob);
    k_main<<<NBLK, 256, SM_TOT>>>();
    k_stats2<<<64, 256>>>(gamma, beta);
    k_bnout<<<NPIX / 64, 256>>>(out);
}